// round 12
// baseline (speedup 1.0000x reference)
#include <cuda_runtime.h>
#include <cstddef>
#include <cstdint>

// Sizes: B=64, S=1024, E=256 (== proj dim), H=1024, G=4*H=4096
#define NB 64
#define NS 1024
#define NE 256
#define NH 1024
#define NG 4096
#define RBLK 128
#define NRES 20                  // smem-resident Wcomb chunks (of 32)

// dynamic smem pool offsets (floats)
#define P2_WRES 0                // 20*2304 = 46080
#define P2_STREAM 46080          // A0,A1,W0,W1 : 4*2304 = 9216
#define P2_GS 46080              // aliases stream area (post-loop use)
#define P1_WS 0                  // 8*2304 = 18432
#define P1_AB 18432              // 4*2304
#define P1_GS 27648              // 64*65 = 4160
#define P3_B 0                   // 32*1028 = 32896
#define P3_A 46080               // 2*2304
#define PW_WHH 0                 // 64*260 = 16640
#define PW_WHR 16640             // 256*68 = 17408
#define POOL_FLOATS 55296        // 221184 bytes

// ---------------- device scratch (static: no runtime allocation) ------------
__device__ float g_xg[2][(size_t)NS * NB * NG];       // 2 GiB  xg [dir][s][b][g]
__device__ float g_xq[(size_t)NB * NS * NE];          // 64 MB  x rounded to tf32
__device__ float g_ah[2][NS + 1][NB * NH];            // 537 MB a history (tf32)
__device__ float g_wc[(size_t)2 * 64 * 32 * 2304];    // 37.7 MB Wcomb, chunk-swizzled tf32
__device__ unsigned g_ctr[4];
__device__ unsigned g_flags[2 * 64];

__device__ __forceinline__ float sigf(float x) { return 1.0f / (1.0f + __expf(-x)); }
__device__ __forceinline__ float tanh_f(float x) {
    float e = __expf(2.0f * x);
    return 1.0f - 2.0f / (e + 1.0f);
}

__device__ __forceinline__ uint4 cvt4(float4 v) {
    uint4 u;
    asm("cvt.rna.tf32.f32 %0, %1;" : "=r"(u.x) : "f"(v.x));
    asm("cvt.rna.tf32.f32 %0, %1;" : "=r"(u.y) : "f"(v.y));
    asm("cvt.rna.tf32.f32 %0, %1;" : "=r"(u.z) : "f"(v.z));
    asm("cvt.rna.tf32.f32 %0, %1;" : "=r"(u.w) : "f"(v.w));
    return u;
}
__device__ __forceinline__ float cvt1(float v) {
    uint32_t u;
    asm("cvt.rna.tf32.f32 %0, %1;" : "=r"(u) : "f"(v));
    return __uint_as_float(u);
}

__device__ __forceinline__ void mma_tf32(float* acc,
                                         uint32_t a0, uint32_t a1, uint32_t a2, uint32_t a3,
                                         uint32_t b0, uint32_t b1) {
    asm volatile(
        "mma.sync.aligned.m16n8k8.row.col.f32.tf32.tf32.f32 "
        "{%0,%1,%2,%3}, {%4,%5,%6,%7}, {%8,%9}, {%0,%1,%2,%3};"
        : "+f"(acc[0]), "+f"(acc[1]), "+f"(acc[2]), "+f"(acc[3])
        : "r"(a0), "r"(a1), "r"(a2), "r"(a3), "r"(b0), "r"(b1));
}

// One 32-wide K chunk. A/B smem row-major stride 36.
template <int NTS>
__device__ __forceinline__ void warp_mma_chunk(const uint32_t* __restrict__ Au,
                                               const uint32_t* __restrict__ Bu,
                                               int mg, int ngb, int l,
                                               float acc[][4]) {
#pragma unroll
    for (int ks = 0; ks < 4; ks++) {
        int k0 = ks * 8 + (l & 3);
        int ra = (mg + (l >> 2)) * 36 + k0;
        uint32_t a0 = Au[ra];
        uint32_t a1 = Au[ra + 8 * 36];
        uint32_t a2 = Au[ra + 4];
        uint32_t a3 = Au[ra + 8 * 36 + 4];
#pragma unroll
        for (int nt = 0; nt < NTS; nt++) {
            int rb = (ngb + nt * 8 + (l >> 2)) * 36 + k0;
            mma_tf32(acc[nt], a0, a1, a2, a3, Bu[rb], Bu[rb + 4]);
        }
    }
}

// 512-thread chunk fill: 64 rows x 32 k, one float4 per thread.
__device__ __forceinline__ void fill512(float* __restrict__ dst,
                                        const float* __restrict__ src,
                                        int stride, int k0, int tid) {
    int r = tid >> 3, kq = (tid & 7) << 2;
    float4 v = __ldcg((const float4*)&src[(size_t)r * stride + k0 + kq]);
    *(float4*)&dst[r * 36 + kq] = v;
}
// raw chunk copy from pre-swizzled g_wc (stride 36 both sides)
__device__ __forceinline__ void fillWc(float* __restrict__ dst,
                                       const float* __restrict__ src, int tid) {
    int r = tid >> 3, kq = (tid & 7) << 2;
    *(float4*)&dst[r * 36 + kq] = __ldcg((const float4*)&src[r * 36 + kq]);
}
// R11-style 256-thread (t2) fill with kg split, for phase 1
__device__ __forceinline__ void fillA_raw(float* __restrict__ dst,
                                          const float* __restrict__ src,
                                          int k0, size_t rowstride, int t2) {
#pragma unroll
    for (int i = 0; i < 2; i++) {
        int f = t2 + i * 256;
        int r = f >> 3;
        int kq = (f & 7) << 2;
        float4 v = __ldcg((const float4*)&src[(size_t)r * rowstride + k0 + kq]);
        *(float4*)&dst[r * 36 + kq] = v;
    }
}

__device__ __forceinline__ unsigned ldacq(const unsigned* p) {
    unsigned v;
    asm volatile("ld.global.acquire.gpu.u32 %0, [%1];" : "=r"(v) : "l"(p) : "memory");
    return v;
}

// Device-scope barrier (phase transitions only): monotonic counter.
__device__ __forceinline__ void gbar(unsigned* c, unsigned target) {
    __syncthreads();
    if (threadIdx.x == 0) {
        __threadfence();
        atomicAdd(c, 1u);
        unsigned v;
        do {
            v = ldacq(c);
        } while (v < target);
    }
    __syncthreads();
}

// --------------------------- init ------------------------------------------
__global__ void init_kernel() {
    int i = blockIdx.x * blockDim.x + threadIdx.x;   // 256 x 512 = 131072
    if (i < 4) g_ctr[i] = 0u;
    if (i < 128) g_flags[i] = 0u;
    if (i < NB * NH) { g_ah[0][0][i] = 0.0f; g_ah[1][0][i] = 0.0f; }
}

// --------------------------- the whole network ------------------------------
__global__ __launch_bounds__(512, 1) void lstm_kernel(
    const float* __restrict__ x,
    const float* __restrict__ Wihf, const float* __restrict__ Whhf,
    const float* __restrict__ bihf, const float* __restrict__ bhhf,
    const float* __restrict__ Whrf,
    const float* __restrict__ Wihb, const float* __restrict__ Whhb,
    const float* __restrict__ bihb, const float* __restrict__ bhhb,
    const float* __restrict__ Whrb,
    float* __restrict__ out)
{
    extern __shared__ __align__(16) float pool[];

    const int bid = blockIdx.x;
    const int tid = threadIdx.x;
    const int l   = tid & 31;
    const int wid = tid >> 5;          // warp 0..15
    const int dir = bid >> 6;
    const int u   = bid & 63;

    // ---------------- phase 0: round x into g_xq ----------------------------
    {
        const size_t n4 = (size_t)NB * NS * NE / 4;
        for (size_t i4 = (size_t)bid * 512 + tid; i4 < n4; i4 += (size_t)RBLK * 512) {
            float4 v = ((const float4*)x)[i4];
            *(uint4*)&((float4*)g_xq)[i4] = cvt4(v);
        }
    }
    gbar(&g_ctr[0], (unsigned)RBLK);

    // ---------------- phase W: Wcomb = Whh @ Whr (fp32, rounded tf32) ------
    // Block (dir,u) computes its 64 gate-col rows x 1024 j, chunk-swizzled.
    {
        const float* __restrict__ WhhW = dir ? Whhb : Whhf;
        const float* __restrict__ WhrW = dir ? Whrb : Whrf;
        float* whh_s = pool + PW_WHH;      // [c][260]
        float* whr_s = pool + PW_WHR;      // [p][68]
        for (int f = tid; f < 64 * 256; f += 512) {
            int c = f >> 8, p = f & 255;
            int g = ((c >> 4) << 10) + (u << 4) + (c & 15);
            whh_s[c * 260 + p] = WhhW[(size_t)g * NE + p];
        }
        __syncthreads();
        const int jj = tid & 63, rg = tid >> 6;
        const size_t wcbase = ((size_t)(dir * 64 + u)) * 32 * 2304;
        for (int jt = 0; jt < 16; jt++) {
            const int j0t = jt * 64;
            for (int f = tid; f < 256 * 64; f += 512) {
                int p = f >> 6, j = f & 63;
                whr_s[p * 68 + j] = WhrW[(size_t)p * NH + j0t + j];
            }
            __syncthreads();
            float acc[8];
#pragma unroll
            for (int i = 0; i < 8; i++) acc[i] = 0.0f;
#pragma unroll 4
            for (int p = 0; p < 256; p++) {
                float wv = whr_s[p * 68 + jj];
#pragma unroll
                for (int i = 0; i < 8; i++)
                    acc[i] += whh_s[(rg * 8 + i) * 260 + p] * wv;
            }
            int j = j0t + jj;
#pragma unroll
            for (int i = 0; i < 8; i++) {
                int r = rg * 8 + i;
                g_wc[wcbase + (size_t)(j >> 5) * 2304 + r * 36 + (j & 31)] = cvt1(acc[i]);
            }
            __syncthreads();
        }
    }

    // ---------------- phase 1: xg = x @ W_ih^T + (b_ih + b_hh) -------------
    {
        const int kg = tid >> 8;
        const int t2 = tid & 255;
        const int wi = t2 >> 5;
        const int mg1 = (wi & 3) << 4;
        const int ngb = (wi >> 2) << 5;
        const int n0 = u << 6;
        const float* __restrict__ W  = dir ? Wihb : Wihf;
        const float* __restrict__ bi = dir ? bihb : bihf;
        const float* __restrict__ bh = dir ? bhhb : bhhf;
        float* __restrict__ xo = g_xg[dir];
        uint32_t* WS = (uint32_t*)(pool + P1_WS);
        float* Ab = pool + P1_AB + kg * 2 * 2304;
        float* gs1 = pool + P1_GS;

#pragma unroll
        for (int ci = 0; ci < 8; ci++) {
            int r = tid >> 3;
            int kq = (tid & 7) << 2;
            float4 wv = *(const float4*)&W[(size_t)(n0 + r) * NE + ci * 32 + kq];
            *(uint4*)&WS[ci * 2304 + r * 36 + kq] = cvt4(wv);
        }
        float bias0[4], bias1[4];
#pragma unroll
        for (int nt = 0; nt < 4; nt++) {
            int c = ngb + nt * 8 + ((l & 3) << 1);
            bias0[nt] = bi[n0 + c] + bh[n0 + c];
            bias1[nt] = bi[n0 + c + 1] + bh[n0 + c + 1];
        }
        __syncthreads();

        for (int s = 0; s < NS; s++) {
            const float* xsrc = g_xq + (size_t)s * NE;
            float acc[4][4];
#pragma unroll
            for (int a = 0; a < 4; a++)
#pragma unroll
                for (int q = 0; q < 4; q++) acc[a][q] = 0.0f;

            fillA_raw(Ab, xsrc, kg * 128, (size_t)NS * NE, t2);
            __syncthreads();
#pragma unroll
            for (int rr = 0; rr < 4; rr++) {
                if (rr < 3)
                    fillA_raw(Ab + ((rr + 1) & 1) * 2304, xsrc,
                              kg * 128 + (rr + 1) * 32, (size_t)NS * NE, t2);
                warp_mma_chunk<4>((uint32_t*)(Ab + (rr & 1) * 2304),
                                  WS + (kg * 4 + rr) * 2304, mg1, ngb, l, acc);
                __syncthreads();
            }
            if (kg == 1) {
#pragma unroll
                for (int nt = 0; nt < 4; nt++) {
                    int c = ngb + nt * 8 + ((l & 3) << 1);
                    int r = mg1 + (l >> 2);
                    gs1[c * 65 + r]           = acc[nt][0];
                    gs1[(c + 1) * 65 + r]     = acc[nt][1];
                    gs1[c * 65 + r + 8]       = acc[nt][2];
                    gs1[(c + 1) * 65 + r + 8] = acc[nt][3];
                }
            }
            __syncthreads();
            if (kg == 0) {
#pragma unroll
                for (int nt = 0; nt < 4; nt++) {
                    int c = ngb + nt * 8 + ((l & 3) << 1);
                    int r = mg1 + (l >> 2);
                    float2 o0, o1;
                    o0.x = acc[nt][0] + gs1[c * 65 + r] + bias0[nt];
                    o0.y = acc[nt][1] + gs1[(c + 1) * 65 + r] + bias1[nt];
                    o1.x = acc[nt][2] + gs1[c * 65 + r + 8] + bias0[nt];
                    o1.y = acc[nt][3] + gs1[(c + 1) * 65 + r + 8] + bias1[nt];
                    __stcs((float2*)&xo[((size_t)s * NB + r) * NG + n0 + c], o0);
                    __stcs((float2*)&xo[((size_t)s * NB + r + 8) * NG + n0 + c], o1);
                }
            }
            __syncthreads();
        }
    }
    gbar(&g_ctr[0], 2u * RBLK);

    // ---------------- phase 2: recurrence, one barrier per step -------------
    {
        const float* __restrict__ xg = g_xg[dir];
        const int j0 = u << 4;
        const int mg = (wid & 3) << 4;
        const int ngb = (wid >> 2) << 4;
        const size_t wcbase = ((size_t)(dir * 64 + u)) * 32 * 2304;
        uint32_t* WresU = (uint32_t*)(pool + P2_WRES);
        float* Sbuf = pool + P2_STREAM;          // A0,A1,W0,W1 (2304 each)
        float* gs2 = pool + P2_GS;               // aliases Sbuf
        unsigned* flg = &g_flags[dir * 64];

        // resident Wcomb chunks
        for (int ci = 0; ci < NRES; ci++)
            fillWc(pool + P2_WRES + ci * 2304, g_wc + wcbase + (size_t)ci * 2304, tid);
        __syncthreads();

        float creg[2] = {0.0f, 0.0f};

        for (int t = 0; t < NS; t++) {
            const int s_eff = dir ? (NS - 1 - t) : t;
            const float* aprev = g_ah[dir][t];
            float* anext = g_ah[dir][t + 1];

            // xg prefetch (independent of flags)
            float xgi[2], xgf[2], xgg[2], xgo[2];
#pragma unroll
            for (int i = 0; i < 2; i++) {
                int m = tid + i * 512;
                int jl = m & 15, b = m >> 4;
                const float* p = &xg[((size_t)s_eff * NB + b) * NG + j0 + jl];
                xgi[i] = __ldcs(p);
                xgf[i] = __ldcs(p + 1024);
                xgg[i] = __ldcs(p + 2048);
                xgo[i] = __ldcs(p + 3072);
            }

            // wait until all 64 producer blocks have published a(t)
            if (tid < 64) {
                while (ldacq(&flg[tid]) < (unsigned)t) { }
            }
            __syncthreads();

            // gates = xg + a(t-..) @ Wcomb^T, K=1024, full-K per warp
            float acc[2][4];
#pragma unroll
            for (int a = 0; a < 2; a++)
#pragma unroll
                for (int q = 0; q < 4; q++) acc[a][q] = 0.0f;

            fill512(Sbuf, aprev, NH, 0, tid);
            __syncthreads();
            for (int ci = 0; ci < 32; ci++) {
                int nx = ci + 1;
                if (nx < 32) {
                    fill512(Sbuf + (nx & 1) * 2304, aprev, NH, nx * 32, tid);
                    if (nx >= NRES)
                        fillWc(Sbuf + 4608 + (nx & 1) * 2304,
                               g_wc + wcbase + (size_t)nx * 2304, tid);
                }
                const uint32_t* Bu = (ci < NRES)
                    ? WresU + ci * 2304
                    : (const uint32_t*)(Sbuf + 4608 + (ci & 1) * 2304);
                warp_mma_chunk<2>((const uint32_t*)(Sbuf + (ci & 1) * 2304),
                                  Bu, mg, ngb, l, acc);
                __syncthreads();
            }

            // stash gates into gs (aliases stream bufs; loop is done)
#pragma unroll
            for (int nt = 0; nt < 2; nt++) {
                int c = ngb + nt * 8 + ((l & 3) << 1);
                int r = mg + (l >> 2);
                gs2[c * 65 + r]           = acc[nt][0];
                gs2[(c + 1) * 65 + r]     = acc[nt][1];
                gs2[c * 65 + r + 8]       = acc[nt][2];
                gs2[(c + 1) * 65 + r + 8] = acc[nt][3];
            }
            __syncthreads();

            // cell update, write rounded a(t+1) into history
#pragma unroll
            for (int i = 0; i < 2; i++) {
                int m = tid + i * 512;
                int jl = m & 15, b = m >> 4;
                float gi = gs2[( 0 + jl) * 65 + b] + xgi[i];
                float gf = gs2[(16 + jl) * 65 + b] + xgf[i];
                float gg = gs2[(32 + jl) * 65 + b] + xgg[i];
                float go = gs2[(48 + jl) * 65 + b] + xgo[i];
                float cn = sigf(gf) * creg[i] + sigf(gi) * tanh_f(gg);
                creg[i] = cn;
                anext[b * NH + j0 + jl] = cvt1(sigf(go) * tanh_f(cn));
            }

            // publish a(t+1): flag := t+1
            __syncthreads();
            if (tid == 0) {
                __threadfence();
                asm volatile("st.global.release.gpu.u32 [%0], %1;"
                             :: "l"(&flg[u]), "r"((unsigned)(t + 1)) : "memory");
            }
        }
    }
    gbar(&g_ctr[0], 3u * RBLK);

    // ---------------- phase 3: out[s] = a_hist @ Whr^T ----------------------
    {
        const int grp = bid & 15;
        const int d3 = grp & 1;
        const int ps = (grp >> 1) << 5;            // 32-wide p stripe
        const int mg3 = (wid & 3) << 4;
        const int n83 = (wid >> 2) << 3;
        const float* __restrict__ Whr3 = d3 ? Whrb : Whrf;
        uint32_t* B3u = (uint32_t*)(pool + P3_B);  // [p 32][1028]
        float* A3 = pool + P3_A;

        for (int f = tid; f < 32 * 256; f += 512) {
            int p = f >> 8, kq = (f & 255) << 2;
            float4 wv = *(const float4*)&Whr3[(size_t)(ps + p) * NH + kq];
            *(uint4*)&B3u[p * 1028 + kq] = cvt4(wv);
        }
        __syncthreads();

        for (int t = bid >> 4; t < NS; t += 8) {
            const float* asrc = g_ah[d3][t + 1];
            const int s_eff = d3 ? (NS - 1 - t) : t;
            float acc[4];
            acc[0] = acc[1] = acc[2] = acc[3] = 0.0f;

            fill512(A3, asrc, NH, 0, tid);
            __syncthreads();
            for (int ci = 0; ci < 32; ci++) {
                if (ci + 1 < 32)
                    fill512(A3 + ((ci + 1) & 1) * 2304, asrc, NH, (ci + 1) * 32, tid);
                const uint32_t* Au = (const uint32_t*)(A3 + (ci & 1) * 2304);
#pragma unroll
                for (int ks = 0; ks < 4; ks++) {
                    int k0l = ks * 8 + (l & 3);
                    int ra = (mg3 + (l >> 2)) * 36 + k0l;
                    uint32_t a0 = Au[ra];
                    uint32_t a1 = Au[ra + 8 * 36];
                    uint32_t a2 = Au[ra + 4];
                    uint32_t a3 = Au[ra + 8 * 36 + 4];
                    int rb = (n83 + (l >> 2)) * 1028 + ci * 32 + k0l;
                    mma_tf32(acc, a0, a1, a2, a3, B3u[rb], B3u[rb + 4]);
                }
                __syncthreads();
            }
            int cc = (l & 3) << 1;
            int r = mg3 + (l >> 2);
            size_t base = (size_t)d3 * 256 + ps + n83 + cc;
            out[((size_t)r * NS + s_eff) * 512 + base]           = acc[0];
            out[((size_t)r * NS + s_eff) * 512 + base + 1]       = acc[1];
            out[((size_t)(r + 8) * NS + s_eff) * 512 + base]     = acc[2];
            out[((size_t)(r + 8) * NS + s_eff) * 512 + base + 1] = acc[3];
        }
    }
}

// ----------------------------- launcher -------------------------------------
extern "C" void kernel_launch(void* const* d_in, const int* in_sizes, int n_in,
                              void* d_out, int out_size) {
    (void)in_sizes; (void)n_in; (void)out_size;
    const float* x    = (const float*)d_in[0];
    const float* Wihf = (const float*)d_in[1];
    const float* Whhf = (const float*)d_in[2];
    const float* bihf = (const float*)d_in[3];
    const float* bhhf = (const float*)d_in[4];
    const float* Whrf = (const float*)d_in[5];
    const float* Wihb = (const float*)d_in[6];
    const float* Whhb = (const float*)d_in[7];
    const float* bihb = (const float*)d_in[8];
    const float* bhhb = (const float*)d_in[9];
    const float* Whrb = (const float*)d_in[10];
    float* out = (float*)d_out;

    cudaFuncSetAttribute(lstm_kernel,
                         cudaFuncAttributeMaxDynamicSharedMemorySize,
                         POOL_FLOATS * 4);
    init_kernel<<<256, 512>>>();
    lstm_kernel<<<RBLK, 512, POOL_FLOATS * 4>>>(
        x, Wihf, Whhf, bihf, bhhf, Whrf,
        Wihb, Whhb, bihb, bhhb, Whrb, out);
}

// round 13
// speedup vs baseline: 2.3362x; 2.3362x over previous
#include <cuda_runtime.h>
#include <cstddef>
#include <cstdint>

// Sizes: B=64, S=1024, E=256 (== proj dim), H=1024, G=4*H=4096
#define NB 64
#define NS 1024
#define NE 256
#define NH 1024
#define NG 4096
#define RBLK 128     // blocks (64 per direction), 1/SM

// dynamic smem pool offsets (floats)
#define WHH_OFF 0                 // 8 chunks x 64 rows x 36      = 18432
#define WHR_OFF 18432             // 16 cols x 1028               = 16448
#define HBUF_OFF 34880            // max(h [64][260]=16640, projA [16][1028]=16448)
#define GS_OFF 51520              // max(64x65, 256x17)           = 4352
#define POOL_FLOATS 55872         // 223488 bytes
// phase-1 aliases
#define P1_WS 0                   // 8*2304 = 18432
#define P1_AB 18432               // 4*2304 = 9216
#define P1_GS 27648               // 64*65  = 4160

// ---------------- device scratch (static: no runtime allocation) ------------
__device__ float g_xg[2][(size_t)NS * NB * NG];  // 2 GiB  xg [dir][s][b][g]
__device__ float g_xq[(size_t)NB * NS * NE];     // 64 MB  x rounded to tf32
__device__ float g_hq[2][2][NB * NE];            // [parity][dir] rounded h
__device__ float g_a[2][NB * NH];                // [dir][b*1024+j] rounded
__device__ unsigned g_ctr[4];
__device__ unsigned g_flags[2 * 64 * 16];        // padded: one flag per 64B

__device__ __forceinline__ float sigf(float x) { return 1.0f / (1.0f + __expf(-x)); }
__device__ __forceinline__ float tanh_f(float x) {
    float e = __expf(2.0f * x);
    return 1.0f - 2.0f / (e + 1.0f);
}

__device__ __forceinline__ uint4 cvt4(float4 v) {
    uint4 u;
    asm("cvt.rna.tf32.f32 %0, %1;" : "=r"(u.x) : "f"(v.x));
    asm("cvt.rna.tf32.f32 %0, %1;" : "=r"(u.y) : "f"(v.y));
    asm("cvt.rna.tf32.f32 %0, %1;" : "=r"(u.z) : "f"(v.z));
    asm("cvt.rna.tf32.f32 %0, %1;" : "=r"(u.w) : "f"(v.w));
    return u;
}
__device__ __forceinline__ float cvt1(float v) {
    uint32_t u;
    asm("cvt.rna.tf32.f32 %0, %1;" : "=r"(u) : "f"(v));
    return __uint_as_float(u);
}

__device__ __forceinline__ void mma_tf32(float* acc,
                                         uint32_t a0, uint32_t a1, uint32_t a2, uint32_t a3,
                                         uint32_t b0, uint32_t b1) {
    asm volatile(
        "mma.sync.aligned.m16n8k8.row.col.f32.tf32.tf32.f32 "
        "{%0,%1,%2,%3}, {%4,%5,%6,%7}, {%8,%9}, {%0,%1,%2,%3};"
        : "+f"(acc[0]), "+f"(acc[1]), "+f"(acc[2]), "+f"(acc[3])
        : "r"(a0), "r"(a1), "r"(a2), "r"(a3), "r"(b0), "r"(b1));
}

// One 32-wide K chunk. A/B smem row-major stride 36 (phase 1 only).
template <int NTS>
__device__ __forceinline__ void warp_mma_chunk(const uint32_t* __restrict__ Au,
                                               const uint32_t* __restrict__ Bu,
                                               int mg, int ngb, int l,
                                               float acc[][4]) {
#pragma unroll
    for (int ks = 0; ks < 4; ks++) {
        int k0 = ks * 8 + (l & 3);
        int ra = (mg + (l >> 2)) * 36 + k0;
        uint32_t a0 = Au[ra];
        uint32_t a1 = Au[ra + 8 * 36];
        uint32_t a2 = Au[ra + 4];
        uint32_t a3 = Au[ra + 8 * 36 + 4];
#pragma unroll
        for (int nt = 0; nt < NTS; nt++) {
            int rb = (ngb + nt * 8 + (l >> 2)) * 36 + k0;
            mma_tf32(acc[nt], a0, a1, a2, a3, Bu[rb], Bu[rb + 4]);
        }
    }
}

// phase-1 A-side chunk fill (256-thread groups, kg split)
__device__ __forceinline__ void fillA_raw(float* __restrict__ dst,
                                          const float* __restrict__ src,
                                          int k0, size_t rowstride, int t2) {
#pragma unroll
    for (int i = 0; i < 2; i++) {
        int f = t2 + i * 256;
        int r = f >> 3;
        int kq = (f & 7) << 2;
        float4 v = __ldcg((const float4*)&src[(size_t)r * rowstride + k0 + kq]);
        *(float4*)&dst[r * 36 + kq] = v;
    }
}

__device__ __forceinline__ unsigned ldacq(const unsigned* p) {
    unsigned v;
    asm volatile("ld.global.acquire.gpu.u32 %0, [%1];" : "=r"(v) : "l"(p) : "memory");
    return v;
}
__device__ __forceinline__ void strel(unsigned* p, unsigned v) {
    asm volatile("st.global.release.gpu.u32 [%0], %1;" :: "l"(p), "r"(v) : "memory");
}

// Device-scope barrier (phase transitions only).
__device__ __forceinline__ void gbar(unsigned* c, unsigned target) {
    __syncthreads();
    if (threadIdx.x == 0) {
        __threadfence();
        atomicAdd(c, 1u);
        unsigned v;
        do { v = ldacq(c); } while (v < target);
    }
    __syncthreads();
}

// --------------------------- init ------------------------------------------
__global__ void init_kernel() {
    int i = blockIdx.x * blockDim.x + threadIdx.x;   // 128 x 512 = 65536
    if (i < 4) g_ctr[i] = 0u;
    if (i < 2 * 64 * 16) g_flags[i] = 0u;
    if (i < 2 * 2 * NB * NE) (&g_hq[0][0][0])[i] = 0.0f;
}

// --------------------------- the whole network ------------------------------
__global__ __launch_bounds__(512, 1) void lstm_kernel(
    const float* __restrict__ x,
    const float* __restrict__ Wihf, const float* __restrict__ Whhf,
    const float* __restrict__ bihf, const float* __restrict__ bhhf,
    const float* __restrict__ Whrf,
    const float* __restrict__ Wihb, const float* __restrict__ Whhb,
    const float* __restrict__ bihb, const float* __restrict__ bhhb,
    const float* __restrict__ Whrb,
    float* __restrict__ out)
{
    extern __shared__ __align__(16) float pool[];

    const int bid = blockIdx.x;
    const int tid = threadIdx.x;
    const int l   = tid & 31;
    const int wid = tid >> 5;          // warp 0..15
    const int dir = bid >> 6;
    const int u   = bid & 63;
    float* gs = pool + GS_OFF;

    // ---------------- phase 0: round x into g_xq ----------------------------
    {
        const size_t n4 = (size_t)NB * NS * NE / 4;
        for (size_t i4 = (size_t)bid * 512 + tid; i4 < n4; i4 += (size_t)RBLK * 512) {
            float4 v = ((const float4*)x)[i4];
            *(uint4*)&((float4*)g_xq)[i4] = cvt4(v);
        }
    }
    gbar(&g_ctr[0], (unsigned)RBLK);

    // ---------------- phase 1: xg = x @ W_ih^T + (b_ih + b_hh) -------------
    {
        const int kg = tid >> 8;
        const int t2 = tid & 255;
        const int wi = t2 >> 5;
        const int mg1 = (wi & 3) << 4;
        const int ngb = (wi >> 2) << 5;
        const int n0 = u << 6;
        const float* __restrict__ W  = dir ? Wihb : Wihf;
        const float* __restrict__ bi = dir ? bihb : bihf;
        const float* __restrict__ bh = dir ? bhhb : bhhf;
        float* __restrict__ xo = g_xg[dir];
        uint32_t* WS = (uint32_t*)(pool + P1_WS);
        float* Ab = pool + P1_AB + kg * 2 * 2304;
        float* gs1 = pool + P1_GS;

#pragma unroll
        for (int ci = 0; ci < 8; ci++) {
            int r = tid >> 3;
            int kq = (tid & 7) << 2;
            float4 wv = *(const float4*)&W[(size_t)(n0 + r) * NE + ci * 32 + kq];
            *(uint4*)&WS[ci * 2304 + r * 36 + kq] = cvt4(wv);
        }
        float bias0[4], bias1[4];
#pragma unroll
        for (int nt = 0; nt < 4; nt++) {
            int c = ngb + nt * 8 + ((l & 3) << 1);
            bias0[nt] = bi[n0 + c] + bh[n0 + c];
            bias1[nt] = bi[n0 + c + 1] + bh[n0 + c + 1];
        }
        __syncthreads();

        for (int s = 0; s < NS; s++) {
            const float* xsrc = g_xq + (size_t)s * NE;
            float acc[4][4];
#pragma unroll
            for (int a = 0; a < 4; a++)
#pragma unroll
                for (int q = 0; q < 4; q++) acc[a][q] = 0.0f;

            fillA_raw(Ab, xsrc, kg * 128, (size_t)NS * NE, t2);
            __syncthreads();
#pragma unroll
            for (int rr = 0; rr < 4; rr++) {
                if (rr < 3)
                    fillA_raw(Ab + ((rr + 1) & 1) * 2304, xsrc,
                              kg * 128 + (rr + 1) * 32, (size_t)NS * NE, t2);
                warp_mma_chunk<4>((uint32_t*)(Ab + (rr & 1) * 2304),
                                  WS + (kg * 4 + rr) * 2304, mg1, ngb, l, acc);
                __syncthreads();
            }
            if (kg == 1) {
#pragma unroll
                for (int nt = 0; nt < 4; nt++) {
                    int c = ngb + nt * 8 + ((l & 3) << 1);
                    int r = mg1 + (l >> 2);
                    gs1[c * 65 + r]           = acc[nt][0];
                    gs1[(c + 1) * 65 + r]     = acc[nt][1];
                    gs1[c * 65 + r + 8]       = acc[nt][2];
                    gs1[(c + 1) * 65 + r + 8] = acc[nt][3];
                }
            }
            __syncthreads();
            if (kg == 0) {
#pragma unroll
                for (int nt = 0; nt < 4; nt++) {
                    int c = ngb + nt * 8 + ((l & 3) << 1);
                    int r = mg1 + (l >> 2);
                    float2 o0, o1;
                    o0.x = acc[nt][0] + gs1[c * 65 + r] + bias0[nt];
                    o0.y = acc[nt][1] + gs1[(c + 1) * 65 + r] + bias1[nt];
                    o1.x = acc[nt][2] + gs1[c * 65 + r + 8] + bias0[nt];
                    o1.y = acc[nt][3] + gs1[(c + 1) * 65 + r + 8] + bias1[nt];
                    __stcs((float2*)&xo[((size_t)s * NB + r) * NG + n0 + c], o0);
                    __stcs((float2*)&xo[((size_t)s * NB + r + 8) * NG + n0 + c], o1);
                }
            }
            __syncthreads();
        }
    }
    gbar(&g_ctr[0], 2u * RBLK);

    // ---------------- phase 2: the recurrence -------------------------------
    const float* __restrict__ Whh = dir ? Whhb : Whhf;
    const float* __restrict__ Whr = dir ? Whrb : Whrf;
    const float* __restrict__ xg  = g_xg[dir];
    unsigned* flg = &g_flags[dir * 64 * 16];

    const int j0 = u << 4;                     // gates: 16 hidden units
    const int b0 = (u >> 4) << 4;              // proj: 16-batch tile
    const int p0 = (u & 15) << 4;              // proj: 16-col tile
    const int mg = (wid & 3) << 4;             // gates m-group (4)
    const int ng2 = (wid >> 2) << 4;           // gates n-group (4 x 16 cols)

    uint32_t* WhhS = (uint32_t*)(pool + WHH_OFF);
    uint32_t* WhrS = (uint32_t*)(pool + WHR_OFF);
    float* hBuf = pool + HBUF_OFF;             // gates: h [64][260]
    float* AP   = pool + HBUF_OFF;             // proj:  a [16][1028] (aliased)

    // ---- load weights into smem ONCE (pre-converted tf32) ------------------
#pragma unroll
    for (int ci = 0; ci < 8; ci++) {
        int r = tid >> 3;
        int kq = (tid & 7) << 2;
        int g = ((r >> 4) << 10) + j0 + (r & 15);
        float4 wv = *(const float4*)&Whh[(size_t)g * NE + ci * 32 + kq];
        *(uint4*)&WhhS[ci * 2304 + r * 36 + kq] = cvt4(wv);
    }
#pragma unroll
    for (int i = 0; i < 8; i++) {
        int f = tid + i * 512;                 // 0..4095
        int c = f >> 8;                        // 0..15
        int kq = (f & 255) << 2;               // 0..1020
        float4 wv = *(const float4*)&Whr[(size_t)(p0 + c) * NH + kq];
        *(uint4*)&WhrS[c * 1028 + kq] = cvt4(wv);
    }
    __syncthreads();

    float creg[2] = {0.0f, 0.0f};              // cell state in registers

    for (int t = 0; t < NS; t++) {
        const int par = t & 1;
        const float* __restrict__ h = g_hq[par][dir];
        const int s_eff = dir ? (NS - 1 - t) : t;

        // prefetch xg for the cell update (mapping: m = tid + i*512)
        float xgi[2], xgf[2], xgg[2], xgo[2];
#pragma unroll
        for (int i = 0; i < 2; i++) {
            int m = tid + i * 512;
            int jl = m & 15, b = m >> 4;
            const float* p = &xg[((size_t)s_eff * NB + b) * NG + j0 + jl];
            xgi[i] = __ldcs(p);
            xgf[i] = __ldcs(p + 1024);
            xgg[i] = __ldcs(p + 2048);
            xgo[i] = __ldcs(p + 3072);
        }

        // ---- wait h(t) published by all blocks (flags >= 2t) --------------
        if (t > 0) {
            if (tid < 64) {
                while (ldacq(&flg[tid * 16]) < (unsigned)(2 * t)) { }
            }
        }
        __syncthreads();

        // ---- gates GEMM: 64b x 64c, K=256, burst-filled h, resident Whh ---
        {
            // burst fill h -> hBuf [64][260], MLP 8
#pragma unroll
            for (int i = 0; i < 8; i++) {
                int f = tid + i * 512;
                int r = f >> 6, q = f & 63;
                float4 v = __ldcg((const float4*)&h[r * NE + (q << 2)]);
                *(float4*)&hBuf[r * 260 + (q << 2)] = v;
            }
            __syncthreads();

            float acc[2][4];
#pragma unroll
            for (int a = 0; a < 2; a++)
#pragma unroll
                for (int q = 0; q < 4; q++) acc[a][q] = 0.0f;

            const uint32_t* hU = (const uint32_t*)hBuf;
#pragma unroll
            for (int ci = 0; ci < 8; ci++) {
#pragma unroll
                for (int ks = 0; ks < 4; ks++) {
                    int k0 = ks * 8 + (l & 3);
                    int ra = (mg + (l >> 2)) * 260 + ci * 32 + k0;
                    uint32_t a0 = hU[ra];
                    uint32_t a1 = hU[ra + 8 * 260];
                    uint32_t a2 = hU[ra + 4];
                    uint32_t a3 = hU[ra + 8 * 260 + 4];
#pragma unroll
                    for (int nt = 0; nt < 2; nt++) {
                        int rb = (ng2 + nt * 8 + (l >> 2)) * 36 + k0;
                        mma_tf32(acc[nt], a0, a1, a2, a3,
                                 WhhS[ci * 2304 + rb], WhhS[ci * 2304 + rb + 4]);
                    }
                }
            }
            // full-K sums: write gates to gs [c][65]
#pragma unroll
            for (int nt = 0; nt < 2; nt++) {
                int c = ng2 + nt * 8 + ((l & 3) << 1);
                int r = mg + (l >> 2);
                gs[c * 65 + r]           = acc[nt][0];
                gs[(c + 1) * 65 + r]     = acc[nt][1];
                gs[c * 65 + r + 8]       = acc[nt][2];
                gs[(c + 1) * 65 + r + 8] = acc[nt][3];
            }
            __syncthreads();
        }

        // ---- cell update (c in registers), rounded a to global ------------
#pragma unroll
        for (int i = 0; i < 2; i++) {
            int m = tid + i * 512;
            int jl = m & 15, b = m >> 4;
            float gi = gs[( 0 + jl) * 65 + b] + xgi[i];
            float gf = gs[(16 + jl) * 65 + b] + xgf[i];
            float gg = gs[(32 + jl) * 65 + b] + xgg[i];
            float go = gs[(48 + jl) * 65 + b] + xgo[i];
            float cn = sigf(gf) * creg[i] + sigf(gi) * tanh_f(gg);
            creg[i] = cn;
            g_a[dir][b * NH + j0 + jl] = cvt1(sigf(go) * tanh_f(cn));
        }
        __syncthreads();
        if (tid == 0) { __threadfence(); strel(&flg[u * 16], (unsigned)(2 * t + 1)); }

        // ---- wait a(t) from all blocks (flags >= 2t+1) --------------------
        if (tid < 64) {
            while (ldacq(&flg[tid * 16]) < (unsigned)(2 * t + 1)) { }
        }
        __syncthreads();

        // ---- projection: h[b0:+16, p0:+16] = a @ Whr^T (full K=1024) ------
        {
#pragma unroll
            for (int i = 0; i < 8; i++) {
                int f = tid + i * 512;
                int r = f >> 8;
                int kq = (f & 255) << 2;
                float4 v = __ldcg((const float4*)&g_a[dir][(size_t)(b0 + r) * NH + kq]);
                *(float4*)&AP[r * 1028 + kq] = v;
            }
            __syncthreads();

            uint32_t* APu = (uint32_t*)AP;
            float pacc[2][4];
#pragma unroll
            for (int nt = 0; nt < 2; nt++)
#pragma unroll
                for (int q = 0; q < 4; q++) pacc[nt][q] = 0.0f;

            const int kw = wid * 64;               // this warp's K slice
#pragma unroll
            for (int ks = 0; ks < 8; ks++) {
                int k0 = kw + ks * 8 + (l & 3);
                int ra = (l >> 2) * 1028 + k0;
                uint32_t a0 = APu[ra];
                uint32_t a1 = APu[ra + 8 * 1028];
                uint32_t a2 = APu[ra + 4];
                uint32_t a3 = APu[ra + 8 * 1028 + 4];
#pragma unroll
                for (int nt = 0; nt < 2; nt++) {
                    int rb = (nt * 8 + (l >> 2)) * 1028 + k0;
                    mma_tf32(pacc[nt], a0, a1, a2, a3, WhrS[rb], WhrS[rb + 4]);
                }
            }
            // partials -> gs [ (r*16+c)*17 + warp ]
#pragma unroll
            for (int nt = 0; nt < 2; nt++) {
                int c0 = nt * 8 + ((l & 3) << 1);
                int r0 = l >> 2;
                gs[(r0 * 16 + c0) * 17 + wid]           = pacc[nt][0];
                gs[(r0 * 16 + c0 + 1) * 17 + wid]       = pacc[nt][1];
                gs[((r0 + 8) * 16 + c0) * 17 + wid]     = pacc[nt][2];
                gs[((r0 + 8) * 16 + c0 + 1) * 17 + wid] = pacc[nt][3];
            }
            __syncthreads();

            // reduce 16 partials, write out + rounded h
            if (tid < 256) {
                float v = 0.0f;
#pragma unroll
                for (int ww = 0; ww < 16; ww++) v += gs[tid * 17 + ww];
                int b = b0 + (tid >> 4);
                int p = p0 + (tid & 15);
                out[((size_t)b * NS + s_eff) * (2 * NE) + dir * NE + p] = v;
                g_hq[par ^ 1][dir][b * NE + p] = cvt1(v);
            }
        }
        __syncthreads();
        if (tid == 0) { __threadfence(); strel(&flg[u * 16], (unsigned)(2 * t + 2)); }
    }
}

// ----------------------------- launcher -------------------------------------
extern "C" void kernel_launch(void* const* d_in, const int* in_sizes, int n_in,
                              void* d_out, int out_size) {
    (void)in_sizes; (void)n_in; (void)out_size;
    const float* x    = (const float*)d_in[0];
    const float* Wihf = (const float*)d_in[1];
    const float* Whhf = (const float*)d_in[2];
    const float* bihf = (const float*)d_in[3];
    const float* bhhf = (const float*)d_in[4];
    const float* Whrf = (const float*)d_in[5];
    const float* Wihb = (const float*)d_in[6];
    const float* Whhb = (const float*)d_in[7];
    const float* bihb = (const float*)d_in[8];
    const float* bhhb = (const float*)d_in[9];
    const float* Whrb = (const float*)d_in[10];
    float* out = (float*)d_out;

    cudaFuncSetAttribute(lstm_kernel,
                         cudaFuncAttributeMaxDynamicSharedMemorySize,
                         POOL_FLOATS * 4);
    init_kernel<<<128, 512>>>();
    lstm_kernel<<<RBLK, 512, POOL_FLOATS * 4>>>(
        x, Wihf, Whhf, bihf, bhhf, Whrf,
        Wihb, Whhb, bihb, bhhb, Whrb, out);
}